// round 8
// baseline (speedup 1.0000x reference)
#include <cuda_runtime.h>
#include <cuda_fp16.h>
#include <cstdint>

#define BB 4
#define SS 4096
#define DD 256
#define NN (BB*SS)

// ---------------- device scratch ----------------
__device__ __half g_src16[NN*DD];
__device__ __half g_Wq16[DD*DD];
__device__ __half g_Wk16[DD*DD];
__device__ __half g_Wv16[DD*DD];
__device__ __half g_Wo16[DD*DD];
__device__ __half g_Qh[NN*DD];
__device__ __half g_Kh[NN*DD];
__device__ __half g_Vth[NN*DD];   // [b][d][s]
__device__ __half g_O16[NN*DD];
__device__ float g_q0[NN];
__device__ float g_k0[NN];

// ---------------- helpers ----------------
#define SWZ(o) ((o) ^ (((o) >> 3) & 0x70))

__device__ __forceinline__ uint32_t smem_u32(const void* p){
    uint32_t a;
    asm("{ .reg .u64 t; cvta.to.shared.u64 t, %1; cvt.u32.u64 %0, t; }" : "=r"(a) : "l"(p));
    return a;
}
__device__ __forceinline__ void sts32(uint32_t a, uint32_t v){
    asm volatile("st.shared.b32 [%0], %1;" :: "r"(a), "r"(v) : "memory");
}
__device__ __forceinline__ void cpa16(uint32_t s, const void* g){
    asm volatile("cp.async.cg.shared.global [%0], [%1], 16;" :: "r"(s), "l"(g) : "memory");
}
#define CPA_COMMIT() asm volatile("cp.async.commit_group;" ::: "memory")
#define CPA_WAIT(n)  asm volatile("cp.async.wait_group %0;" :: "n"(n) : "memory")

__device__ __forceinline__ float ex2f(float x){
    float y; asm("ex2.approx.f32 %0, %1;" : "=f"(y) : "f"(x)); return y;
}

#define LDMX4(d0,d1,d2,d3,a) \
    asm volatile("ldmatrix.sync.aligned.m8n8.x4.shared.b16 {%0,%1,%2,%3}, [%4];" \
                 : "=r"(d0),"=r"(d1),"=r"(d2),"=r"(d3) : "r"(a))
#define MMA16816(c,a0,a1,a2,a3,b0,b1) \
    asm volatile("mma.sync.aligned.m16n8k16.row.col.f32.f16.f16.f32 " \
                 "{%0,%1,%2,%3},{%4,%5,%6,%7},{%8,%9},{%0,%1,%2,%3};" \
                 : "+f"((c)[0]),"+f"((c)[1]),"+f"((c)[2]),"+f"((c)[3]) \
                 : "r"(a0),"r"(a1),"r"(a2),"r"(a3),"r"(b0),"r"(b1))

// blocked-atom swizzled smem address of 16B chunk (r, c16); apg = atoms per 8-row group
__device__ __forceinline__ uint32_t tadr(uint32_t base, int r, int c16, int apg){
    return base + (uint32_t)(((((r>>3)*apg + (c16>>3))<<10)) +
                             SWZ((uint32_t)(((r&7)<<7) | ((c16&7)<<4))));
}

// ---------------------------------------------------------------------------
// cvt_kernel: fp32 -> fp16 single, float4 granularity
// ---------------------------------------------------------------------------
__global__ __launch_bounds__(256) void cvt_kernel(
    const float4* __restrict__ in, uint2* __restrict__ out, int n4)
{
    int i = blockIdx.x * 256 + threadIdx.x;
    if (i >= n4) return;
    float4 v = in[i];
    __half2 h01 = __floats2half2_rn(v.x, v.y);
    __half2 h23 = __floats2half2_rn(v.z, v.w);
    out[i] = make_uint2(*reinterpret_cast<uint32_t*>(&h01),
                        *reinterpret_cast<uint32_t*>(&h23));
}

// ---------------------------------------------------------------------------
// proj1: C = A W^T + bias, single fp16 MMA, fp32 accumulate.
// CTA 128x128, 8 warps (4M x 2N). Full K=256 resident in smem.
// mode 0: outH fp16 (val*scale) row-major + col0 fp32
// mode 2: outH fp16 transposed [b][d][s]
// mode 3: outF fp32 row-major
// ---------------------------------------------------------------------------
#define PJ_SMEM (131072 + 1024)

__global__ __launch_bounds__(256, 1) void proj1(
    const __half* __restrict__ A16, const __half* __restrict__ W16,
    const float* __restrict__ bias,
    __half* __restrict__ outH, float* __restrict__ outF,
    float* __restrict__ col0, int mode, float scale)
{
    extern __shared__ char psm[];
    const uint32_t raw = smem_u32(psm);
    const uint32_t abase = (raw + 1023u) & ~1023u;
    char* cbase = psm + (abase - raw);
    const uint32_t aA = abase, aW = abase + 65536u;

    const int tid = threadIdx.x, wid = tid >> 5, lane = tid & 31;
    const int mi = wid >> 1, ni = wid & 1;
    const int i0 = blockIdx.x * 128, j0 = blockIdx.y * 128;

    const int mat = lane >> 3, lr = lane & 7;
    const int arow = (mat & 1) * 8 + lr;
    const int asel = mat >> 1;
    const int brow = ((mat >> 1) << 3) + lr;
    const int bsel = mat & 1;

    const uint4* A4 = reinterpret_cast<const uint4*>(A16);
    const uint4* W4 = reinterpret_cast<const uint4*>(W16);

    #pragma unroll
    for (int t = 0; t < 16; t++) {
        int idx = tid + t * 256;
        int r = idx >> 5, c = idx & 31;
        cpa16(tadr(aA, r, c, 4), A4 + (size_t)(i0 + r)*32 + c);
        cpa16(tadr(aW, r, c, 4), W4 + (size_t)(j0 + r)*32 + c);
    }
    CPA_COMMIT();

    float oacc[2][8][4];
    #pragma unroll
    for (int m2 = 0; m2 < 2; m2++)
        #pragma unroll
        for (int nf = 0; nf < 8; nf++)
            #pragma unroll
            for (int j = 0; j < 4; j++) oacc[m2][nf][j] = 0.0f;

    CPA_WAIT(0);
    __syncthreads();

    #pragma unroll 4
    for (int ks = 0; ks < 16; ks++) {
        uint32_t a[2][4];
        #pragma unroll
        for (int m2 = 0; m2 < 2; m2++)
            LDMX4(a[m2][0],a[m2][1],a[m2][2],a[m2][3],
                  tadr(aA, mi*32 + m2*16 + arow, 2*ks + asel, 4));
        #pragma unroll
        for (int n16 = 0; n16 < 4; n16++) {
            uint32_t b0,b1,b2,b3;
            LDMX4(b0,b1,b2,b3, tadr(aW, ni*64 + n16*16 + brow, 2*ks + bsel, 4));
            #pragma unroll
            for (int m2 = 0; m2 < 2; m2++) {
                MMA16816(oacc[m2][n16*2  ], a[m2][0],a[m2][1],a[m2][2],a[m2][3], b0,b1);
                MMA16816(oacc[m2][n16*2+1], a[m2][0],a[m2][1],a[m2][2],a[m2][3], b2,b3);
            }
        }
    }

    const int r0 = lane >> 2, cb = lane & 3;

    if (mode == 2) {
        __syncthreads();
        float* st = reinterpret_cast<float*>(cbase);
        #pragma unroll
        for (int m2 = 0; m2 < 2; m2++)
            #pragma unroll
            for (int nf = 0; nf < 8; nf++) {
                int r = mi*32 + m2*16 + r0;
                int c = ni*64 + nf*8 + cb*2;
                float b0v = bias[j0 + c], b1v = bias[j0 + c + 1];
                st[r*129 + c]       = oacc[m2][nf][0] + b0v;
                st[r*129 + c + 1]   = oacc[m2][nf][1] + b1v;
                st[(r+8)*129 + c]   = oacc[m2][nf][2] + b0v;
                st[(r+8)*129 + c+1] = oacc[m2][nf][3] + b1v;
            }
        __syncthreads();
        const int b = i0 >> 12, s0 = i0 & 4095;
        uint4* V4o = reinterpret_cast<uint4*>(outH);
        #pragma unroll
        for (int t = 0; t < 8; t++) {
            int idx = tid + t * 256;
            int dl = idx >> 4, sc = idx & 15;
            uint32_t hh[4];
            #pragma unroll
            for (int e = 0; e < 4; e++) {
                __half2 h2 = __floats2half2_rn(st[(sc*8 + 2*e)*129 + dl],
                                               st[(sc*8 + 2*e + 1)*129 + dl]);
                hh[e] = *reinterpret_cast<uint32_t*>(&h2);
            }
            V4o[((size_t)(b*DD + j0 + dl))*512 + (s0 >> 3) + sc] =
                make_uint4(hh[0], hh[1], hh[2], hh[3]);
        }
        return;
    }

    #pragma unroll
    for (int m2 = 0; m2 < 2; m2++)
        #pragma unroll
        for (int nf = 0; nf < 8; nf++) {
            int r = mi*32 + m2*16 + r0;
            int c = ni*64 + nf*8 + cb*2;
            float b0v = bias[j0 + c], b1v = bias[j0 + c + 1];
            float v00 = oacc[m2][nf][0] + b0v, v01 = oacc[m2][nf][1] + b1v;
            float v10 = oacc[m2][nf][2] + b0v, v11 = oacc[m2][nf][3] + b1v;
            size_t n0 = (size_t)(i0 + r), n1 = n0 + 8;
            if (mode == 0) {
                if (col0 && j0 + c == 0) { col0[n0] = v00; col0[n1] = v10; }
                __half2 a2 = __floats2half2_rn(v00*scale, v01*scale);
                __half2 c2 = __floats2half2_rn(v10*scale, v11*scale);
                reinterpret_cast<uint32_t*>(outH)[(n0*DD + j0 + c) >> 1] =
                    *reinterpret_cast<uint32_t*>(&a2);
                reinterpret_cast<uint32_t*>(outH)[(n1*DD + j0 + c) >> 1] =
                    *reinterpret_cast<uint32_t*>(&c2);
            } else {   // mode 3
                reinterpret_cast<float2*>(outF)[(n0*DD + j0 + c) >> 1] = make_float2(v00, v01);
                reinterpret_cast<float2*>(outF)[(n1*DD + j0 + c) >> 1] = make_float2(v10, v11);
            }
        }
}

// ---------------------------------------------------------------------------
// flash_mma: 512 threads (16 warps, 4/SMSP). Q pre-scaled by log2e/16 so
// softmax is a raw ex2. Warp grid: mi=wid>>2 (rows), ni=wid&3.
// MMA1 warp tile 32x16, MMA2 warp tile 32x64. O fp16 out.
// ---------------------------------------------------------------------------
#define OFF_Q    0u
#define OFF_K0   65536u
#define OFF_K1   98304u
#define OFF_V0   131072u
#define OFF_V1   163840u
#define OFF_P    196608u
#define FL_SMEM  (212992 + 1024)

__global__ __launch_bounds__(512, 1) void flash_mma(
    const __half* __restrict__ Qh_, const __half* __restrict__ Kh_,
    const __half* __restrict__ Vth_,
    const float* __restrict__ q0g, const float* __restrict__ k0g,
    __half* __restrict__ O16)
{
    extern __shared__ char fsm[];
    const uint32_t raw = smem_u32(fsm);
    const uint32_t abase = (raw + 1023u) & ~1023u;
    char* cbase = fsm + (abase - raw);
    const uint32_t aQ = abase + OFF_Q;
    const uint32_t aK[2] = { abase + OFF_K0, abase + OFF_K1 };
    const uint32_t aV[2] = { abase + OFF_V0, abase + OFF_V1 };
    const uint32_t aP = abase + OFF_P;

    const int tid = threadIdx.x, wid = tid >> 5, lane = tid & 31;
    const int mi = wid >> 2, ni = wid & 3;
    const int b = blockIdx.y, i0 = blockIdx.x * 128;

    const int mat = lane >> 3, lr = lane & 7;
    const int arow = (mat & 1) * 8 + lr;
    const int asel = mat >> 1;
    const int brow = ((mat >> 1) << 3) + lr;
    const int bsel = mat & 1;

    const uint4* Qg4 = reinterpret_cast<const uint4*>(Qh_) + ((size_t)(b*SS + i0)) * 32;
    const uint4* Kg4 = reinterpret_cast<const uint4*>(Kh_) + (size_t)b*SS*32;
    const uint4* Vg4 = reinterpret_cast<const uint4*>(Vth_) + (size_t)b*DD*512;

    #pragma unroll
    for (int t = 0; t < 8; t++) {
        int idx = tid + t * 512;          // 0..4095
        int r = idx >> 5, c = idx & 31;
        cpa16(tadr(aQ, r, c, 4), Qg4 + (size_t)r*32 + c);
    }
    CPA_COMMIT();
    #pragma unroll
    for (int t = 0; t < 4; t++) {
        int idx = tid + t * 512;          // 0..2047
        int r = idx >> 5, c = idx & 31;
        cpa16(tadr(aK[0], r, c, 4), Kg4 + (size_t)r*32 + c);
    }
    CPA_COMMIT();
    #pragma unroll
    for (int t = 0; t < 4; t++) {
        int idx = tid + t * 512;
        int r = idx >> 3, c = idx & 7;
        cpa16(tadr(aV[0], r, c, 1), Vg4 + (size_t)r*512 + c);
    }
    CPA_COMMIT();

    float oacc[2][8][4];
    #pragma unroll
    for (int m2 = 0; m2 < 2; m2++)
        #pragma unroll
        for (int nf = 0; nf < 8; nf++)
            #pragma unroll
            for (int j = 0; j < 4; j++) oacc[m2][nf][j] = 0.0f;
    float lsum[2][2] = {{0.f,0.f},{0.f,0.f}};

    for (int kt = 0; kt < SS/64; kt++) {
        const int buf = kt & 1;
        __syncthreads();
        if (kt + 1 < SS/64) {
            const int nb = buf ^ 1;
            #pragma unroll
            for (int t = 0; t < 4; t++) {
                int idx = tid + t * 512;
                int r = idx >> 5, c = idx & 31;
                cpa16(tadr(aK[nb], r, c, 4), Kg4 + (size_t)((kt+1)*64 + r)*32 + c);
            }
            CPA_COMMIT();
            #pragma unroll
            for (int t = 0; t < 4; t++) {
                int idx = tid + t * 512;
                int r = idx >> 3, c = idx & 7;
                cpa16(tadr(aV[nb], r, c, 1), Vg4 + (size_t)r*512 + (kt+1)*8 + c);
            }
            CPA_COMMIT();
            CPA_WAIT(2);
        } else {
            CPA_WAIT(0);
        }
        __syncthreads();

        // ---- MMA1: S = Q K^T (warp tile 32x16) ----
        float sacc[2][2][4];
        #pragma unroll
        for (int m2 = 0; m2 < 2; m2++)
            #pragma unroll
            for (int n8 = 0; n8 < 2; n8++)
                #pragma unroll
                for (int j = 0; j < 4; j++) sacc[m2][n8][j] = 0.0f;

        #pragma unroll 4
        for (int ks = 0; ks < 16; ks++) {
            uint32_t a[2][4];
            #pragma unroll
            for (int m2 = 0; m2 < 2; m2++)
                LDMX4(a[m2][0],a[m2][1],a[m2][2],a[m2][3],
                      tadr(aQ, mi*32 + m2*16 + arow, 2*ks + asel, 4));
            uint32_t b0,b1,b2,b3;
            LDMX4(b0,b1,b2,b3, tadr(aK[buf], ni*16 + brow, 2*ks + bsel, 4));
            #pragma unroll
            for (int m2 = 0; m2 < 2; m2++) {
                MMA16816(sacc[m2][0], a[m2][0],a[m2][1],a[m2][2],a[m2][3], b0,b1);
                MMA16816(sacc[m2][1], a[m2][0],a[m2][1],a[m2][2],a[m2][3], b2,b3);
            }
        }

        // ---- softmax: exp2 (log2e folded into Q scale) -> P fp16 ----
        {
            const int r0l = lane >> 2;
            const int ib = (lane & 3) * 4;
            #pragma unroll
            for (int m2 = 0; m2 < 2; m2++) {
                int row = mi*32 + m2*16 + r0l;
                #pragma unroll
                for (int n8 = 0; n8 < 2; n8++) {
                    float e0 = ex2f(sacc[m2][n8][0]);
                    float e1 = ex2f(sacc[m2][n8][1]);
                    float e2 = ex2f(sacc[m2][n8][2]);
                    float e3 = ex2f(sacc[m2][n8][3]);
                    lsum[m2][0] += e0 + e1;
                    lsum[m2][1] += e2 + e3;
                    __half2 h01 = __floats2half2_rn(e0, e1);
                    __half2 h23 = __floats2half2_rn(e2, e3);
                    sts32(tadr(aP, row,     2*ni + n8, 1) + ib,
                          *reinterpret_cast<uint32_t*>(&h01));
                    sts32(tadr(aP, row + 8, 2*ni + n8, 1) + ib,
                          *reinterpret_cast<uint32_t*>(&h23));
                }
            }
        }
        // strip barrier: 4 warps sharing rows mi*32..+32 exchange P
        asm volatile("bar.sync %0, %1;" :: "r"(mi + 1), "r"(128) : "memory");

        // ---- MMA2: O += P V (warp tile 32x64) ----
        #pragma unroll
        for (int ks = 0; ks < 4; ks++) {
            uint32_t a[2][4];
            #pragma unroll
            for (int m2 = 0; m2 < 2; m2++)
                LDMX4(a[m2][0],a[m2][1],a[m2][2],a[m2][3],
                      tadr(aP, mi*32 + m2*16 + arow, 2*ks + asel, 1));
            #pragma unroll
            for (int n16 = 0; n16 < 4; n16++) {
                uint32_t b0,b1,b2,b3;
                LDMX4(b0,b1,b2,b3,
                      tadr(aV[buf], ni*64 + n16*16 + brow, 2*ks + bsel, 1));
                #pragma unroll
                for (int m2 = 0; m2 < 2; m2++) {
                    MMA16816(oacc[m2][n16*2  ], a[m2][0],a[m2][1],a[m2][2],a[m2][3], b0,b1);
                    MMA16816(oacc[m2][n16*2+1], a[m2][0],a[m2][1],a[m2][2],a[m2][3], b2,b3);
                }
            }
        }
    }

    // ---- epilogue: combine lsum across 4 ni warps, mask, normalize, store ----
    __syncthreads();
    float* Lsh = reinterpret_cast<float*>(cbase + OFF_P);   // 128 rows x 4
    {
        const int r0l = lane >> 2;
        #pragma unroll
        for (int m2 = 0; m2 < 2; m2++)
            #pragma unroll
            for (int h = 0; h < 2; h++) {
                float v = lsum[m2][h];
                v += __shfl_xor_sync(0xffffffff, v, 1);
                v += __shfl_xor_sync(0xffffffff, v, 2);
                if ((lane & 3) == 0)
                    Lsh[(mi*32 + m2*16 + h*8 + r0l)*4 + ni] = v;
            }
    }
    __syncthreads();
    {
        const int r0l = lane >> 2, cb = lane & 3;
        #pragma unroll
        for (int m2 = 0; m2 < 2; m2++) {
            int row0 = mi*32 + m2*16 + r0l;
            size_t g0 = (size_t)b*SS + i0 + row0;
            size_t g1 = g0 + 8;
            float l0 = Lsh[row0*4] + Lsh[row0*4+1] + Lsh[row0*4+2] + Lsh[row0*4+3];
            float l1 = Lsh[(row0+8)*4] + Lsh[(row0+8)*4+1] + Lsh[(row0+8)*4+2] + Lsh[(row0+8)*4+3];
            float mf0 = (q0g[g0] != 0.0f && k0g[g0] != 0.0f) ? (1.0f / l0) : 0.0f;
            float mf1 = (q0g[g1] != 0.0f && k0g[g1] != 0.0f) ? (1.0f / l1) : 0.0f;
            uint32_t* H0 = reinterpret_cast<uint32_t*>(O16 + g0*DD);
            uint32_t* H1 = reinterpret_cast<uint32_t*>(O16 + g1*DD);
            #pragma unroll
            for (int nf = 0; nf < 8; nf++) {
                int f2 = ni*32 + nf*4 + cb;
                __half2 a2 = __floats2half2_rn(oacc[m2][nf][0]*mf0, oacc[m2][nf][1]*mf0);
                __half2 c2 = __floats2half2_rn(oacc[m2][nf][2]*mf1, oacc[m2][nf][3]*mf1);
                H0[f2] = *reinterpret_cast<uint32_t*>(&a2);
                H1[f2] = *reinterpret_cast<uint32_t*>(&c2);
            }
        }
    }
}

// ---------------------------------------------------------------------------
extern "C" void kernel_launch(void* const* d_in, const int* in_sizes, int n_in,
                              void* d_out, int out_size)
{
    const float* src = (const float*)d_in[0];
    const float* Wq  = (const float*)d_in[1];
    const float* bq  = (const float*)d_in[2];
    const float* Wk  = (const float*)d_in[3];
    const float* bk  = (const float*)d_in[4];
    const float* Wv  = (const float*)d_in[5];
    const float* bv  = (const float*)d_in[6];
    const float* Wo  = (const float*)d_in[7];
    const float* bo  = (const float*)d_in[8];
    float* out = (float*)d_out;

    __half *pS,*pWq,*pWk,*pWv,*pWo,*pQ,*pK,*pV,*pO;
    float *pq0,*pk0;
    cudaGetSymbolAddress((void**)&pS, g_src16);
    cudaGetSymbolAddress((void**)&pWq, g_Wq16);
    cudaGetSymbolAddress((void**)&pWk, g_Wk16);
    cudaGetSymbolAddress((void**)&pWv, g_Wv16);
    cudaGetSymbolAddress((void**)&pWo, g_Wo16);
    cudaGetSymbolAddress((void**)&pQ, g_Qh);
    cudaGetSymbolAddress((void**)&pK, g_Kh);
    cudaGetSymbolAddress((void**)&pV, g_Vth);
    cudaGetSymbolAddress((void**)&pO, g_O16);
    cudaGetSymbolAddress((void**)&pq0, g_q0);
    cudaGetSymbolAddress((void**)&pk0, g_k0);

    cvt_kernel<<<(NN*DD/4 + 255)/256, 256>>>((const float4*)src, (uint2*)pS, NN*DD/4);
    cvt_kernel<<<(DD*DD/4 + 255)/256, 256>>>((const float4*)Wq, (uint2*)pWq, DD*DD/4);
    cvt_kernel<<<(DD*DD/4 + 255)/256, 256>>>((const float4*)Wk, (uint2*)pWk, DD*DD/4);
    cvt_kernel<<<(DD*DD/4 + 255)/256, 256>>>((const float4*)Wv, (uint2*)pWv, DD*DD/4);
    cvt_kernel<<<(DD*DD/4 + 255)/256, 256>>>((const float4*)Wo, (uint2*)pWo, DD*DD/4);

    cudaFuncSetAttribute(proj1, cudaFuncAttributeMaxDynamicSharedMemorySize, PJ_SMEM);
    dim3 pg(NN/128, DD/128);   // (128, 2)
    // Q scale = (1/sqrt(256)) * log2(e)  -> softmax becomes raw exp2
    proj1<<<pg, 256, PJ_SMEM>>>(pS, pWq, bq, pQ, nullptr, pq0, 0, 0.0901684761047f);
    proj1<<<pg, 256, PJ_SMEM>>>(pS, pWk, bk, pK, nullptr, pk0, 0, 1.0f);
    proj1<<<pg, 256, PJ_SMEM>>>(pS, pWv, bv, pV, nullptr, nullptr, 2, 1.0f);

    cudaFuncSetAttribute(flash_mma, cudaFuncAttributeMaxDynamicSharedMemorySize, FL_SMEM);
    flash_mma<<<dim3(SS/128, BB), 512, FL_SMEM>>>(pQ, pK, pV, pq0, pk0, pO);

    proj1<<<pg, 256, PJ_SMEM>>>(pO, pWo, bo, nullptr, out, nullptr, 3, 1.0f);
}

// round 9
// speedup vs baseline: 1.1261x; 1.1261x over previous
#include <cuda_runtime.h>
#include <cuda_fp16.h>
#include <cstdint>

#define BB 4
#define SS 4096
#define DD 256
#define NN (BB*SS)

// ---------------- device scratch ----------------
__device__ __half g_src16[NN*DD];
__device__ __half g_Wq16[DD*DD];
__device__ __half g_Wk16[DD*DD];
__device__ __half g_Wv16[DD*DD];
__device__ __half g_Wo16[DD*DD];
__device__ __half g_Qh[NN*DD];
__device__ __half g_Kh[NN*DD];
__device__ __half g_Vth[NN*DD];   // [b][d][s]
__device__ __half g_O16[NN*DD];
__device__ float g_q0[NN];
__device__ float g_k0[NN];

// ---------------- helpers ----------------
#define SWZ(o) ((o) ^ (((o) >> 3) & 0x70))

__device__ __forceinline__ uint32_t smem_u32(const void* p){
    uint32_t a;
    asm("{ .reg .u64 t; cvta.to.shared.u64 t, %1; cvt.u32.u64 %0, t; }" : "=r"(a) : "l"(p));
    return a;
}
__device__ __forceinline__ void sts32(uint32_t a, uint32_t v){
    asm volatile("st.shared.b32 [%0], %1;" :: "r"(a), "r"(v) : "memory");
}
__device__ __forceinline__ void cpa16(uint32_t s, const void* g){
    asm volatile("cp.async.cg.shared.global [%0], [%1], 16;" :: "r"(s), "l"(g) : "memory");
}
#define CPA_COMMIT() asm volatile("cp.async.commit_group;" ::: "memory")
#define CPA_WAIT(n)  asm volatile("cp.async.wait_group %0;" :: "n"(n) : "memory")

__device__ __forceinline__ float ex2f(float x){
    float y; asm("ex2.approx.f32 %0, %1;" : "=f"(y) : "f"(x)); return y;
}

#define LDMX4(d0,d1,d2,d3,a) \
    asm volatile("ldmatrix.sync.aligned.m8n8.x4.shared.b16 {%0,%1,%2,%3}, [%4];" \
                 : "=r"(d0),"=r"(d1),"=r"(d2),"=r"(d3) : "r"(a))
#define MMA16816(c,a0,a1,a2,a3,b0,b1) \
    asm volatile("mma.sync.aligned.m16n8k16.row.col.f32.f16.f16.f32 " \
                 "{%0,%1,%2,%3},{%4,%5,%6,%7},{%8,%9},{%0,%1,%2,%3};" \
                 : "+f"((c)[0]),"+f"((c)[1]),"+f"((c)[2]),"+f"((c)[3]) \
                 : "r"(a0),"r"(a1),"r"(a2),"r"(a3),"r"(b0),"r"(b1))

// blocked-atom swizzled smem address of 16B chunk (r, c16); apg = atoms per 8-row group
__device__ __forceinline__ uint32_t tadr(uint32_t base, int r, int c16, int apg){
    return base + (uint32_t)(((((r>>3)*apg + (c16>>3))<<10)) +
                             SWZ((uint32_t)(((r&7)<<7) | ((c16&7)<<4))));
}

// ---------------------------------------------------------------------------
// cvt_kernel: fp32 -> fp16 single, float4 granularity
// ---------------------------------------------------------------------------
__global__ __launch_bounds__(256) void cvt_kernel(
    const float4* __restrict__ in, uint2* __restrict__ out, int n4)
{
    int i = blockIdx.x * 256 + threadIdx.x;
    if (i >= n4) return;
    float4 v = in[i];
    __half2 h01 = __floats2half2_rn(v.x, v.y);
    __half2 h23 = __floats2half2_rn(v.z, v.w);
    out[i] = make_uint2(*reinterpret_cast<uint32_t*>(&h01),
                        *reinterpret_cast<uint32_t*>(&h23));
}

// ---------------------------------------------------------------------------
// proj1: C = A W^T + bias, single fp16 MMA, fp32 accumulate.
// CTA 128x128, 8 warps (4M x 2N). Full K=256 resident in smem.
// mode 0: outH fp16 (val*scale) row-major + col0 fp32
// mode 2: outH fp16 transposed [b][d][s]
// mode 3: outF fp32 row-major
// ---------------------------------------------------------------------------
#define PJ_SMEM (131072 + 1024)

__global__ __launch_bounds__(256, 1) void proj1(
    const __half* __restrict__ A16, const __half* __restrict__ W16,
    const float* __restrict__ bias,
    __half* __restrict__ outH, float* __restrict__ outF,
    float* __restrict__ col0, int mode, float scale)
{
    extern __shared__ char psm[];
    const uint32_t raw = smem_u32(psm);
    const uint32_t abase = (raw + 1023u) & ~1023u;
    char* cbase = psm + (abase - raw);
    const uint32_t aA = abase, aW = abase + 65536u;

    const int tid = threadIdx.x, wid = tid >> 5, lane = tid & 31;
    const int mi = wid >> 1, ni = wid & 1;
    const int i0 = blockIdx.x * 128, j0 = blockIdx.y * 128;

    const int mat = lane >> 3, lr = lane & 7;
    const int arow = (mat & 1) * 8 + lr;
    const int asel = mat >> 1;
    const int brow = ((mat >> 1) << 3) + lr;
    const int bsel = mat & 1;

    const uint4* A4 = reinterpret_cast<const uint4*>(A16);
    const uint4* W4 = reinterpret_cast<const uint4*>(W16);

    #pragma unroll
    for (int t = 0; t < 16; t++) {
        int idx = tid + t * 256;
        int r = idx >> 5, c = idx & 31;
        cpa16(tadr(aA, r, c, 4), A4 + (size_t)(i0 + r)*32 + c);
        cpa16(tadr(aW, r, c, 4), W4 + (size_t)(j0 + r)*32 + c);
    }
    CPA_COMMIT();

    float oacc[2][8][4];
    #pragma unroll
    for (int m2 = 0; m2 < 2; m2++)
        #pragma unroll
        for (int nf = 0; nf < 8; nf++)
            #pragma unroll
            for (int j = 0; j < 4; j++) oacc[m2][nf][j] = 0.0f;

    CPA_WAIT(0);
    __syncthreads();

    #pragma unroll 4
    for (int ks = 0; ks < 16; ks++) {
        uint32_t a[2][4];
        #pragma unroll
        for (int m2 = 0; m2 < 2; m2++)
            LDMX4(a[m2][0],a[m2][1],a[m2][2],a[m2][3],
                  tadr(aA, mi*32 + m2*16 + arow, 2*ks + asel, 4));
        #pragma unroll
        for (int n16 = 0; n16 < 4; n16++) {
            uint32_t b0,b1,b2,b3;
            LDMX4(b0,b1,b2,b3, tadr(aW, ni*64 + n16*16 + brow, 2*ks + bsel, 4));
            #pragma unroll
            for (int m2 = 0; m2 < 2; m2++) {
                MMA16816(oacc[m2][n16*2  ], a[m2][0],a[m2][1],a[m2][2],a[m2][3], b0,b1);
                MMA16816(oacc[m2][n16*2+1], a[m2][0],a[m2][1],a[m2][2],a[m2][3], b2,b3);
            }
        }
    }

    const int r0 = lane >> 2, cb = lane & 3;

    if (mode == 2) {
        __syncthreads();
        float* st = reinterpret_cast<float*>(cbase);
        #pragma unroll
        for (int m2 = 0; m2 < 2; m2++)
            #pragma unroll
            for (int nf = 0; nf < 8; nf++) {
                int r = mi*32 + m2*16 + r0;
                int c = ni*64 + nf*8 + cb*2;
                float b0v = bias[j0 + c], b1v = bias[j0 + c + 1];
                st[r*129 + c]       = oacc[m2][nf][0] + b0v;
                st[r*129 + c + 1]   = oacc[m2][nf][1] + b1v;
                st[(r+8)*129 + c]   = oacc[m2][nf][2] + b0v;
                st[(r+8)*129 + c+1] = oacc[m2][nf][3] + b1v;
            }
        __syncthreads();
        const int b = i0 >> 12, s0 = i0 & 4095;
        uint4* V4o = reinterpret_cast<uint4*>(outH);
        #pragma unroll
        for (int t = 0; t < 8; t++) {
            int idx = tid + t * 256;
            int dl = idx >> 4, sc = idx & 15;
            uint32_t hh[4];
            #pragma unroll
            for (int e = 0; e < 4; e++) {
                __half2 h2 = __floats2half2_rn(st[(sc*8 + 2*e)*129 + dl],
                                               st[(sc*8 + 2*e + 1)*129 + dl]);
                hh[e] = *reinterpret_cast<uint32_t*>(&h2);
            }
            V4o[((size_t)(b*DD + j0 + dl))*512 + (s0 >> 3) + sc] =
                make_uint4(hh[0], hh[1], hh[2], hh[3]);
        }
        return;
    }

    #pragma unroll
    for (int m2 = 0; m2 < 2; m2++)
        #pragma unroll
        for (int nf = 0; nf < 8; nf++) {
            int r = mi*32 + m2*16 + r0;
            int c = ni*64 + nf*8 + cb*2;
            float b0v = bias[j0 + c], b1v = bias[j0 + c + 1];
            float v00 = oacc[m2][nf][0] + b0v, v01 = oacc[m2][nf][1] + b1v;
            float v10 = oacc[m2][nf][2] + b0v, v11 = oacc[m2][nf][3] + b1v;
            size_t n0 = (size_t)(i0 + r), n1 = n0 + 8;
            if (mode == 0) {
                if (col0 && j0 + c == 0) { col0[n0] = v00; col0[n1] = v10; }
                __half2 a2 = __floats2half2_rn(v00*scale, v01*scale);
                __half2 c2 = __floats2half2_rn(v10*scale, v11*scale);
                reinterpret_cast<uint32_t*>(outH)[(n0*DD + j0 + c) >> 1] =
                    *reinterpret_cast<uint32_t*>(&a2);
                reinterpret_cast<uint32_t*>(outH)[(n1*DD + j0 + c) >> 1] =
                    *reinterpret_cast<uint32_t*>(&c2);
            } else {   // mode 3
                reinterpret_cast<float2*>(outF)[(n0*DD + j0 + c) >> 1] = make_float2(v00, v01);
                reinterpret_cast<float2*>(outF)[(n1*DD + j0 + c) >> 1] = make_float2(v10, v11);
            }
        }
}

// ---------------------------------------------------------------------------
// flash_mma: 256 threads, 8 warps (4M x 2N, warp tiles 32x32 / 32x128).
// Q pre-scaled by log2e/16 so softmax is a raw ex2. O fp16 out.
// ---------------------------------------------------------------------------
#define OFF_Q    0u
#define OFF_K0   65536u
#define OFF_K1   98304u
#define OFF_V0   131072u
#define OFF_V1   163840u
#define OFF_P    196608u
#define FL_SMEM  (212992 + 1024)

__global__ __launch_bounds__(256, 1) void flash_mma(
    const __half* __restrict__ Qh_, const __half* __restrict__ Kh_,
    const __half* __restrict__ Vth_,
    const float* __restrict__ q0g, const float* __restrict__ k0g,
    __half* __restrict__ O16)
{
    extern __shared__ char fsm[];
    const uint32_t raw = smem_u32(fsm);
    const uint32_t abase = (raw + 1023u) & ~1023u;
    char* cbase = fsm + (abase - raw);
    const uint32_t aQ = abase + OFF_Q;
    const uint32_t aK[2] = { abase + OFF_K0, abase + OFF_K1 };
    const uint32_t aV[2] = { abase + OFF_V0, abase + OFF_V1 };
    const uint32_t aP = abase + OFF_P;

    const int tid = threadIdx.x, wid = tid >> 5, lane = tid & 31;
    const int mi = wid >> 1, ni = wid & 1;
    const int b = blockIdx.y, i0 = blockIdx.x * 128;

    const int mat = lane >> 3, lr = lane & 7;
    const int arow = (mat & 1) * 8 + lr;
    const int asel = mat >> 1;
    const int brow = ((mat >> 1) << 3) + lr;
    const int bsel = mat & 1;

    const uint4* Qg4 = reinterpret_cast<const uint4*>(Qh_) + ((size_t)(b*SS + i0)) * 32;
    const uint4* Kg4 = reinterpret_cast<const uint4*>(Kh_) + (size_t)b*SS*32;
    const uint4* Vg4 = reinterpret_cast<const uint4*>(Vth_) + (size_t)b*DD*512;

    #pragma unroll
    for (int t = 0; t < 16; t++) {
        int idx = tid + t * 256;
        int r = idx >> 5, c = idx & 31;
        cpa16(tadr(aQ, r, c, 4), Qg4 + (size_t)r*32 + c);
    }
    CPA_COMMIT();
    #pragma unroll
    for (int t = 0; t < 8; t++) {
        int idx = tid + t * 256;
        int r = idx >> 5, c = idx & 31;
        cpa16(tadr(aK[0], r, c, 4), Kg4 + (size_t)r*32 + c);
    }
    CPA_COMMIT();
    #pragma unroll
    for (int t = 0; t < 8; t++) {
        int idx = tid + t * 256;
        int r = idx >> 3, c = idx & 7;
        cpa16(tadr(aV[0], r, c, 1), Vg4 + (size_t)r*512 + c);
    }
    CPA_COMMIT();

    float oacc[2][16][4];
    #pragma unroll
    for (int m2 = 0; m2 < 2; m2++)
        #pragma unroll
        for (int nf = 0; nf < 16; nf++)
            #pragma unroll
            for (int j = 0; j < 4; j++) oacc[m2][nf][j] = 0.0f;
    float lsum[2][2] = {{0.f,0.f},{0.f,0.f}};

    for (int kt = 0; kt < SS/64; kt++) {
        const int buf = kt & 1;
        __syncthreads();
        if (kt + 1 < SS/64) {
            const int nb = buf ^ 1;
            #pragma unroll
            for (int t = 0; t < 8; t++) {
                int idx = tid + t * 256;
                int r = idx >> 5, c = idx & 31;
                cpa16(tadr(aK[nb], r, c, 4), Kg4 + (size_t)((kt+1)*64 + r)*32 + c);
            }
            CPA_COMMIT();
            #pragma unroll
            for (int t = 0; t < 8; t++) {
                int idx = tid + t * 256;
                int r = idx >> 3, c = idx & 7;
                cpa16(tadr(aV[nb], r, c, 1), Vg4 + (size_t)r*512 + (kt+1)*8 + c);
            }
            CPA_COMMIT();
            CPA_WAIT(2);
        } else {
            CPA_WAIT(0);
        }
        __syncthreads();

        // ---- MMA1: S = Q K^T (warp tile 32x32) ----
        float sacc[2][4][4];
        #pragma unroll
        for (int m2 = 0; m2 < 2; m2++)
            #pragma unroll
            for (int nf = 0; nf < 4; nf++)
                #pragma unroll
                for (int j = 0; j < 4; j++) sacc[m2][nf][j] = 0.0f;

        #pragma unroll 4
        for (int ks = 0; ks < 16; ks++) {
            uint32_t a[2][4];
            #pragma unroll
            for (int m2 = 0; m2 < 2; m2++)
                LDMX4(a[m2][0],a[m2][1],a[m2][2],a[m2][3],
                      tadr(aQ, mi*32 + m2*16 + arow, 2*ks + asel, 4));
            #pragma unroll
            for (int n16 = 0; n16 < 2; n16++) {
                uint32_t b0,b1,b2,b3;
                LDMX4(b0,b1,b2,b3,
                      tadr(aK[buf], ni*32 + n16*16 + brow, 2*ks + bsel, 4));
                #pragma unroll
                for (int m2 = 0; m2 < 2; m2++) {
                    MMA16816(sacc[m2][n16*2  ], a[m2][0],a[m2][1],a[m2][2],a[m2][3], b0,b1);
                    MMA16816(sacc[m2][n16*2+1], a[m2][0],a[m2][1],a[m2][2],a[m2][3], b2,b3);
                }
            }
        }

        // ---- softmax: raw exp2 (log2e folded into Q scale) -> P fp16 ----
        {
            const int r0 = lane >> 2;
            const int ib = (lane & 3) * 4;
            #pragma unroll
            for (int m2 = 0; m2 < 2; m2++) {
                #pragma unroll
                for (int nf = 0; nf < 4; nf++) {
                    float e0 = ex2f(sacc[m2][nf][0]);
                    float e1 = ex2f(sacc[m2][nf][1]);
                    float e2 = ex2f(sacc[m2][nf][2]);
                    float e3 = ex2f(sacc[m2][nf][3]);
                    lsum[m2][0] += e0 + e1;
                    lsum[m2][1] += e2 + e3;
                    __half2 h01 = __floats2half2_rn(e0, e1);
                    __half2 h23 = __floats2half2_rn(e2, e3);
                    int row = mi*32 + m2*16 + r0;
                    sts32(tadr(aP, row,     ni*4 + nf, 1) + ib,
                          *reinterpret_cast<uint32_t*>(&h01));
                    sts32(tadr(aP, row + 8, ni*4 + nf, 1) + ib,
                          *reinterpret_cast<uint32_t*>(&h23));
                }
            }
        }
        // pair barrier: the 2 warps sharing rows mi*32..+32 exchange P halves
        asm volatile("bar.sync %0, %1;" :: "r"(mi + 1), "r"(64) : "memory");

        // ---- MMA2: O += P V (warp tile 32x128) ----
        #pragma unroll
        for (int ks = 0; ks < 4; ks++) {
            uint32_t a[2][4];
            #pragma unroll
            for (int m2 = 0; m2 < 2; m2++)
                LDMX4(a[m2][0],a[m2][1],a[m2][2],a[m2][3],
                      tadr(aP, mi*32 + m2*16 + arow, 2*ks + asel, 1));
            #pragma unroll
            for (int n16 = 0; n16 < 8; n16++) {
                uint32_t b0,b1,b2,b3;
                LDMX4(b0,b1,b2,b3,
                      tadr(aV[buf], ni*128 + n16*16 + brow, 2*ks + bsel, 1));
                #pragma unroll
                for (int m2 = 0; m2 < 2; m2++) {
                    MMA16816(oacc[m2][n16*2  ], a[m2][0],a[m2][1],a[m2][2],a[m2][3], b0,b1);
                    MMA16816(oacc[m2][n16*2+1], a[m2][0],a[m2][1],a[m2][2],a[m2][3], b2,b3);
                }
            }
        }
    }

    // ---- epilogue: combine lsum across ni pairs, mask, normalize, store ----
    __syncthreads();
    float* Lsh = reinterpret_cast<float*>(cbase + OFF_P);
    {
        const int r0 = lane >> 2;
        #pragma unroll
        for (int m2 = 0; m2 < 2; m2++)
            #pragma unroll
            for (int h = 0; h < 2; h++) {
                float v = lsum[m2][h];
                v += __shfl_xor_sync(0xffffffff, v, 1);
                v += __shfl_xor_sync(0xffffffff, v, 2);
                if ((lane & 3) == 0)
                    Lsh[(mi*32 + m2*16 + h*8 + r0)*2 + ni] = v;
            }
    }
    __syncthreads();
    {
        const int r0 = lane >> 2;
        #pragma unroll
        for (int m2 = 0; m2 < 2; m2++) {
            int row0 = mi*32 + m2*16 + r0;
            size_t g0 = (size_t)b*SS + i0 + row0;
            size_t g1 = g0 + 8;
            float l0 = Lsh[row0*2] + Lsh[row0*2 + 1];
            float l1 = Lsh[(row0+8)*2] + Lsh[(row0+8)*2 + 1];
            float mf0 = (q0g[g0] != 0.0f && k0g[g0] != 0.0f) ? (1.0f / l0) : 0.0f;
            float mf1 = (q0g[g1] != 0.0f && k0g[g1] != 0.0f) ? (1.0f / l1) : 0.0f;
            uint32_t* H0 = reinterpret_cast<uint32_t*>(O16 + g0*DD);
            uint32_t* H1 = reinterpret_cast<uint32_t*>(O16 + g1*DD);
            int cb = lane & 3;
            #pragma unroll
            for (int nf = 0; nf < 16; nf++) {
                int f2 = ni*64 + nf*4 + cb;
                __half2 a2 = __floats2half2_rn(oacc[m2][nf][0]*mf0, oacc[m2][nf][1]*mf0);
                __half2 c2 = __floats2half2_rn(oacc[m2][nf][2]*mf1, oacc[m2][nf][3]*mf1);
                H0[f2] = *reinterpret_cast<uint32_t*>(&a2);
                H1[f2] = *reinterpret_cast<uint32_t*>(&c2);
            }
        }
    }
}

// ---------------------------------------------------------------------------
extern "C" void kernel_launch(void* const* d_in, const int* in_sizes, int n_in,
                              void* d_out, int out_size)
{
    const float* src = (const float*)d_in[0];
    const float* Wq  = (const float*)d_in[1];
    const float* bq  = (const float*)d_in[2];
    const float* Wk  = (const float*)d_in[3];
    const float* bk  = (const float*)d_in[4];
    const float* Wv  = (const float*)d_in[5];
    const float* bv  = (const float*)d_in[6];
    const float* Wo  = (const float*)d_in[7];
    const float* bo  = (const float*)d_in[8];
    float* out = (float*)d_out;

    __half *pS,*pWq,*pWk,*pWv,*pWo,*pQ,*pK,*pV,*pO;
    float *pq0,*pk0;
    cudaGetSymbolAddress((void**)&pS, g_src16);
    cudaGetSymbolAddress((void**)&pWq, g_Wq16);
    cudaGetSymbolAddress((void**)&pWk, g_Wk16);
    cudaGetSymbolAddress((void**)&pWv, g_Wv16);
    cudaGetSymbolAddress((void**)&pWo, g_Wo16);
    cudaGetSymbolAddress((void**)&pQ, g_Qh);
    cudaGetSymbolAddress((void**)&pK, g_Kh);
    cudaGetSymbolAddress((void**)&pV, g_Vth);
    cudaGetSymbolAddress((void**)&pO, g_O16);
    cudaGetSymbolAddress((void**)&pq0, g_q0);
    cudaGetSymbolAddress((void**)&pk0, g_k0);

    cvt_kernel<<<(NN*DD/4 + 255)/256, 256>>>((const float4*)src, (uint2*)pS, NN*DD/4);
    cvt_kernel<<<(DD*DD/4 + 255)/256, 256>>>((const float4*)Wq, (uint2*)pWq, DD*DD/4);
    cvt_kernel<<<(DD*DD/4 + 255)/256, 256>>>((const float4*)Wk, (uint2*)pWk, DD*DD/4);
    cvt_kernel<<<(DD*DD/4 + 255)/256, 256>>>((const float4*)Wv, (uint2*)pWv, DD*DD/4);
    cvt_kernel<<<(DD*DD/4 + 255)/256, 256>>>((const float4*)Wo, (uint2*)pWo, DD*DD/4);

    cudaFuncSetAttribute(proj1, cudaFuncAttributeMaxDynamicSharedMemorySize, PJ_SMEM);
    dim3 pg(NN/128, DD/128);   // (128, 2)
    // Q scale = (1/sqrt(256)) * log2(e)  -> softmax becomes raw exp2
    proj1<<<pg, 256, PJ_SMEM>>>(pS, pWq, bq, pQ, nullptr, pq0, 0, 0.0901684761047f);
    proj1<<<pg, 256, PJ_SMEM>>>(pS, pWk, bk, pK, nullptr, pk0, 0, 1.0f);
    proj1<<<pg, 256, PJ_SMEM>>>(pS, pWv, bv, pV, nullptr, nullptr, 2, 1.0f);

    cudaFuncSetAttribute(flash_mma, cudaFuncAttributeMaxDynamicSharedMemorySize, FL_SMEM);
    flash_mma<<<dim3(SS/128, BB), 256, FL_SMEM>>>(pQ, pK, pV, pq0, pk0, pO);

    proj1<<<pg, 256, PJ_SMEM>>>(pO, pWo, bo, nullptr, out, nullptr, 3, 1.0f);
}

// round 10
// speedup vs baseline: 1.1808x; 1.0486x over previous
#include <cuda_runtime.h>
#include <cuda_fp16.h>
#include <cstdint>

#define BB 4
#define SS 4096
#define DD 256
#define NN (BB*SS)

// ---------------- device scratch ----------------
__device__ __half g_src16[NN*DD];
__device__ __half g_Wq16[DD*DD];
__device__ __half g_Wk16[DD*DD];
__device__ __half g_Wv16[DD*DD];
__device__ __half g_Wo16[DD*DD];
__device__ __half g_Qh[NN*DD];
__device__ __half g_Kh[NN*DD];
__device__ __half g_Vth[NN*DD];   // [b][d][s]
__device__ __half g_O16[NN*DD];
__device__ float g_q0[NN];
__device__ float g_k0[NN];

// ---------------- helpers ----------------
#define SWZ(o) ((o) ^ (((o) >> 3) & 0x70))

__device__ __forceinline__ uint32_t smem_u32(const void* p){
    uint32_t a;
    asm("{ .reg .u64 t; cvta.to.shared.u64 t, %1; cvt.u32.u64 %0, t; }" : "=r"(a) : "l"(p));
    return a;
}
__device__ __forceinline__ void sts32(uint32_t a, uint32_t v){
    asm volatile("st.shared.b32 [%0], %1;" :: "r"(a), "r"(v) : "memory");
}
__device__ __forceinline__ void cpa16(uint32_t s, const void* g){
    asm volatile("cp.async.cg.shared.global [%0], [%1], 16;" :: "r"(s), "l"(g) : "memory");
}
#define CPA_COMMIT() asm volatile("cp.async.commit_group;" ::: "memory")
#define CPA_WAIT(n)  asm volatile("cp.async.wait_group %0;" :: "n"(n) : "memory")

__device__ __forceinline__ float ex2f(float x){
    float y; asm("ex2.approx.f32 %0, %1;" : "=f"(y) : "f"(x)); return y;
}

#define LDMX4(d0,d1,d2,d3,a) \
    asm volatile("ldmatrix.sync.aligned.m8n8.x4.shared.b16 {%0,%1,%2,%3}, [%4];" \
                 : "=r"(d0),"=r"(d1),"=r"(d2),"=r"(d3) : "r"(a))
#define MMA16816(c,a0,a1,a2,a3,b0,b1) \
    asm volatile("mma.sync.aligned.m16n8k16.row.col.f32.f16.f16.f32 " \
                 "{%0,%1,%2,%3},{%4,%5,%6,%7},{%8,%9},{%0,%1,%2,%3};" \
                 : "+f"((c)[0]),"+f"((c)[1]),"+f"((c)[2]),"+f"((c)[3]) \
                 : "r"(a0),"r"(a1),"r"(a2),"r"(a3),"r"(b0),"r"(b1))

// blocked-atom swizzled smem address of 16B chunk (r, c16); apg = atoms per 8-row group
__device__ __forceinline__ uint32_t tadr(uint32_t base, int r, int c16, int apg){
    return base + (uint32_t)(((((r>>3)*apg + (c16>>3))<<10)) +
                             SWZ((uint32_t)(((r&7)<<7) | ((c16&7)<<4))));
}

// ---------------------------------------------------------------------------
// cvt_kernel: fp32 -> fp16 single (src); cvt_w4: 4 weight matrices, 1 launch
// ---------------------------------------------------------------------------
__global__ __launch_bounds__(256) void cvt_kernel(
    const float4* __restrict__ in, uint2* __restrict__ out, int n4)
{
    int i = blockIdx.x * 256 + threadIdx.x;
    if (i >= n4) return;
    float4 v = in[i];
    __half2 h01 = __floats2half2_rn(v.x, v.y);
    __half2 h23 = __floats2half2_rn(v.z, v.w);
    out[i] = make_uint2(*reinterpret_cast<uint32_t*>(&h01),
                        *reinterpret_cast<uint32_t*>(&h23));
}

__global__ __launch_bounds__(256) void cvt_w4(
    const float4* __restrict__ w0, const float4* __restrict__ w1,
    const float4* __restrict__ w2, const float4* __restrict__ w3,
    uint2* __restrict__ o0, uint2* __restrict__ o1,
    uint2* __restrict__ o2, uint2* __restrict__ o3)
{
    const float4* in; uint2* out;
    switch (blockIdx.y) {
        case 0: in = w0; out = o0; break;
        case 1: in = w1; out = o1; break;
        case 2: in = w2; out = o2; break;
        default: in = w3; out = o3; break;
    }
    int i = blockIdx.x * 256 + threadIdx.x;   // grid.x = 64 -> 16384 f4
    float4 v = in[i];
    __half2 h01 = __floats2half2_rn(v.x, v.y);
    __half2 h23 = __floats2half2_rn(v.z, v.w);
    out[i] = make_uint2(*reinterpret_cast<uint32_t*>(&h01),
                        *reinterpret_cast<uint32_t*>(&h23));
}

// ---------------------------------------------------------------------------
// shared MMA phase: C(128x128) = A(128x256) W^T, fragments per 8-warp 4Mx2N
// ---------------------------------------------------------------------------
__device__ __forceinline__ void mma_phase(
    uint32_t aA, uint32_t bW, int mi, int ni,
    int arow, int asel, int brow, int bsel, float oacc[2][8][4])
{
    #pragma unroll
    for (int m2 = 0; m2 < 2; m2++)
        #pragma unroll
        for (int nf = 0; nf < 8; nf++)
            #pragma unroll
            for (int j = 0; j < 4; j++) oacc[m2][nf][j] = 0.0f;

    #pragma unroll 4
    for (int ks = 0; ks < 16; ks++) {
        uint32_t a[2][4];
        #pragma unroll
        for (int m2 = 0; m2 < 2; m2++)
            LDMX4(a[m2][0],a[m2][1],a[m2][2],a[m2][3],
                  tadr(aA, mi*32 + m2*16 + arow, 2*ks + asel, 4));
        #pragma unroll
        for (int n16 = 0; n16 < 4; n16++) {
            uint32_t b0,b1,b2,b3;
            LDMX4(b0,b1,b2,b3, tadr(bW, ni*64 + n16*16 + brow, 2*ks + bsel, 4));
            #pragma unroll
            for (int m2 = 0; m2 < 2; m2++) {
                MMA16816(oacc[m2][n16*2  ], a[m2][0],a[m2][1],a[m2][2],a[m2][3], b0,b1);
                MMA16816(oacc[m2][n16*2+1], a[m2][0],a[m2][1],a[m2][2],a[m2][3], b2,b3);
            }
        }
    }
}

// fp16 row-major epilogue with scale + optional col0 capture
__device__ __forceinline__ void epi_rowmajor(
    float oacc[2][8][4], const float* bias, __half* outH, float* col0,
    float scale, int i0, int j0, int mi, int ni, int lane)
{
    const int r0 = lane >> 2, cb = lane & 3;
    #pragma unroll
    for (int m2 = 0; m2 < 2; m2++)
        #pragma unroll
        for (int nf = 0; nf < 8; nf++) {
            int r = mi*32 + m2*16 + r0;
            int c = ni*64 + nf*8 + cb*2;
            float b0v = bias[j0 + c], b1v = bias[j0 + c + 1];
            float v00 = oacc[m2][nf][0] + b0v, v01 = oacc[m2][nf][1] + b1v;
            float v10 = oacc[m2][nf][2] + b0v, v11 = oacc[m2][nf][3] + b1v;
            size_t n0 = (size_t)(i0 + r), n1 = n0 + 8;
            if (col0 && j0 + c == 0) { col0[n0] = v00; col0[n1] = v10; }
            __half2 a2 = __floats2half2_rn(v00*scale, v01*scale);
            __half2 c2 = __floats2half2_rn(v10*scale, v11*scale);
            reinterpret_cast<uint32_t*>(outH)[(n0*DD + j0 + c) >> 1] =
                *reinterpret_cast<uint32_t*>(&a2);
            reinterpret_cast<uint32_t*>(outH)[(n1*DD + j0 + c) >> 1] =
                *reinterpret_cast<uint32_t*>(&c2);
        }
}

// ---------------------------------------------------------------------------
// proj_qkv: fused Q/K/V projections. A tile loaded once; W tiles streamed
// through 2 cp.async buffers. V written transposed [b][d][s] via staged smem.
// SMEM: A 64K | W0 64K | W1 64K = 192K
// ---------------------------------------------------------------------------
#define QKV_SMEM (196608 + 1024)

__global__ __launch_bounds__(256, 1) void proj_qkv(
    const __half* __restrict__ A16,
    const __half* __restrict__ Wq16, const __half* __restrict__ Wk16,
    const __half* __restrict__ Wv16,
    const float* __restrict__ bq, const float* __restrict__ bk,
    const float* __restrict__ bv,
    __half* __restrict__ Qh, __half* __restrict__ Kh, __half* __restrict__ Vt,
    float* __restrict__ q0, float* __restrict__ k0, float qscale)
{
    extern __shared__ char psm[];
    const uint32_t raw = smem_u32(psm);
    const uint32_t abase = (raw + 1023u) & ~1023u;
    char* cbase = psm + (abase - raw);
    const uint32_t aA = abase;
    const uint32_t aW0 = abase + 65536u, aW1 = abase + 131072u;

    const int tid = threadIdx.x, wid = tid >> 5, lane = tid & 31;
    const int mi = wid >> 1, ni = wid & 1;
    const int i0 = blockIdx.x * 128, j0 = blockIdx.y * 128;

    const int mat = lane >> 3, lr = lane & 7;
    const int arow = (mat & 1) * 8 + lr;
    const int asel = mat >> 1;
    const int brow = ((mat >> 1) << 3) + lr;
    const int bsel = mat & 1;

    const uint4* A4  = reinterpret_cast<const uint4*>(A16);
    const uint4* Wq4 = reinterpret_cast<const uint4*>(Wq16);
    const uint4* Wk4 = reinterpret_cast<const uint4*>(Wk16);
    const uint4* Wv4 = reinterpret_cast<const uint4*>(Wv16);

    // group1: A, group2: Wq->W0, group3: Wk->W1
    #pragma unroll
    for (int t = 0; t < 16; t++) {
        int idx = tid + t * 256;
        int r = idx >> 5, c = idx & 31;
        cpa16(tadr(aA, r, c, 4), A4 + (size_t)(i0 + r)*32 + c);
    }
    CPA_COMMIT();
    #pragma unroll
    for (int t = 0; t < 16; t++) {
        int idx = tid + t * 256;
        int r = idx >> 5, c = idx & 31;
        cpa16(tadr(aW0, r, c, 4), Wq4 + (size_t)(j0 + r)*32 + c);
    }
    CPA_COMMIT();
    #pragma unroll
    for (int t = 0; t < 16; t++) {
        int idx = tid + t * 256;
        int r = idx >> 5, c = idx & 31;
        cpa16(tadr(aW1, r, c, 4), Wk4 + (size_t)(j0 + r)*32 + c);
    }
    CPA_COMMIT();

    float oacc[2][8][4];

    // ---- Q phase ----
    CPA_WAIT(1);           // A + Wq done
    __syncthreads();
    mma_phase(aA, aW0, mi, ni, arow, asel, brow, bsel, oacc);
    __syncthreads();       // all warps done reading W0
    // group4: Wv -> W0
    #pragma unroll
    for (int t = 0; t < 16; t++) {
        int idx = tid + t * 256;
        int r = idx >> 5, c = idx & 31;
        cpa16(tadr(aW0, r, c, 4), Wv4 + (size_t)(j0 + r)*32 + c);
    }
    CPA_COMMIT();
    epi_rowmajor(oacc, bq, Qh, q0, qscale, i0, j0, mi, ni, lane);  // overlaps Wv loads

    // ---- K phase ----
    CPA_WAIT(1);           // Wk done (Wv in flight)
    __syncthreads();
    mma_phase(aA, aW1, mi, ni, arow, asel, brow, bsel, oacc);
    epi_rowmajor(oacc, bk, Kh, k0, 1.0f, i0, j0, mi, ni, lane);

    // ---- V phase ----
    CPA_WAIT(0);           // Wv done
    __syncthreads();       // also guarantees all warps done reading W1 (K MMAs)
    mma_phase(aA, aW0, mi, ni, arow, asel, brow, bsel, oacc);

    // V epilogue: transposed write via staged fp32 tile in W1 region (dead),
    // two 64-row passes (64 x 129 fp32 = 33 KB <= 64 KB)
    {
        float* st = reinterpret_cast<float*>(cbase + 131072);
        const int r0 = lane >> 2, cb = lane & 3;
        const int b = i0 >> 12, s0 = i0 & 4095;
        uint4* V4o = reinterpret_cast<uint4*>(Vt);
        #pragma unroll
        for (int p = 0; p < 2; p++) {
            __syncthreads();
            if ((mi >> 1) == p) {
                #pragma unroll
                for (int m2 = 0; m2 < 2; m2++)
                    #pragma unroll
                    for (int nf = 0; nf < 8; nf++) {
                        int r = (mi & 1)*32 + m2*16 + r0;      // 0..63
                        int c = ni*64 + nf*8 + cb*2;
                        float b0v = bv[j0 + c], b1v = bv[j0 + c + 1];
                        st[r*129 + c]       = oacc[m2][nf][0] + b0v;
                        st[r*129 + c + 1]   = oacc[m2][nf][1] + b1v;
                        st[(r+8)*129 + c]   = oacc[m2][nf][2] + b0v;
                        st[(r+8)*129 + c+1] = oacc[m2][nf][3] + b1v;
                    }
            }
            __syncthreads();
            #pragma unroll
            for (int t = 0; t < 4; t++) {
                int idx = tid + t * 256;       // 0..1023
                int dl = idx >> 3, sc = idx & 7;
                uint32_t hh[4];
                #pragma unroll
                for (int e = 0; e < 4; e++) {
                    __half2 h2 = __floats2half2_rn(st[(sc*8 + 2*e)*129 + dl],
                                                   st[(sc*8 + 2*e + 1)*129 + dl]);
                    hh[e] = *reinterpret_cast<uint32_t*>(&h2);
                }
                V4o[((size_t)(b*DD + j0 + dl))*512 + (s0 >> 3) + p*8 + sc] =
                    make_uint4(hh[0], hh[1], hh[2], hh[3]);
            }
        }
    }
}

// ---------------------------------------------------------------------------
// proj1 (mode 3 only): final Wo projection, fp32 out
// ---------------------------------------------------------------------------
#define PJ_SMEM (131072 + 1024)

__global__ __launch_bounds__(256, 1) void proj1(
    const __half* __restrict__ A16, const __half* __restrict__ W16,
    const float* __restrict__ bias, float* __restrict__ outF)
{
    extern __shared__ char psm[];
    const uint32_t raw = smem_u32(psm);
    const uint32_t abase = (raw + 1023u) & ~1023u;
    const uint32_t aA = abase, aW = abase + 65536u;

    const int tid = threadIdx.x, wid = tid >> 5, lane = tid & 31;
    const int mi = wid >> 1, ni = wid & 1;
    const int i0 = blockIdx.x * 128, j0 = blockIdx.y * 128;

    const int mat = lane >> 3, lr = lane & 7;
    const int arow = (mat & 1) * 8 + lr;
    const int asel = mat >> 1;
    const int brow = ((mat >> 1) << 3) + lr;
    const int bsel = mat & 1;

    const uint4* A4 = reinterpret_cast<const uint4*>(A16);
    const uint4* W4 = reinterpret_cast<const uint4*>(W16);

    #pragma unroll
    for (int t = 0; t < 16; t++) {
        int idx = tid + t * 256;
        int r = idx >> 5, c = idx & 31;
        cpa16(tadr(aA, r, c, 4), A4 + (size_t)(i0 + r)*32 + c);
        cpa16(tadr(aW, r, c, 4), W4 + (size_t)(j0 + r)*32 + c);
    }
    CPA_COMMIT();

    float oacc[2][8][4];
    CPA_WAIT(0);
    __syncthreads();
    mma_phase(aA, aW, mi, ni, arow, asel, brow, bsel, oacc);

    const int r0 = lane >> 2, cb = lane & 3;
    #pragma unroll
    for (int m2 = 0; m2 < 2; m2++)
        #pragma unroll
        for (int nf = 0; nf < 8; nf++) {
            int r = mi*32 + m2*16 + r0;
            int c = ni*64 + nf*8 + cb*2;
            float b0v = bias[j0 + c], b1v = bias[j0 + c + 1];
            size_t n0 = (size_t)(i0 + r), n1 = n0 + 8;
            reinterpret_cast<float2*>(outF)[(n0*DD + j0 + c) >> 1] =
                make_float2(oacc[m2][nf][0] + b0v, oacc[m2][nf][1] + b1v);
            reinterpret_cast<float2*>(outF)[(n1*DD + j0 + c) >> 1] =
                make_float2(oacc[m2][nf][2] + b0v, oacc[m2][nf][3] + b1v);
        }
}

// ---------------------------------------------------------------------------
// flash_mma: 256 threads, 8 warps (4M x 2N, warp tiles 32x32 / 32x128).
// Q pre-scaled by log2e/16 so softmax is a raw ex2. O fp16 out.
// (frozen from the 277 us round)
// ---------------------------------------------------------------------------
#define OFF_Q    0u
#define OFF_K0   65536u
#define OFF_K1   98304u
#define OFF_V0   131072u
#define OFF_V1   163840u
#define OFF_P    196608u
#define FL_SMEM  (212992 + 1024)

__global__ __launch_bounds__(256, 1) void flash_mma(
    const __half* __restrict__ Qh_, const __half* __restrict__ Kh_,
    const __half* __restrict__ Vth_,
    const float* __restrict__ q0g, const float* __restrict__ k0g,
    __half* __restrict__ O16)
{
    extern __shared__ char fsm[];
    const uint32_t raw = smem_u32(fsm);
    const uint32_t abase = (raw + 1023u) & ~1023u;
    char* cbase = fsm + (abase - raw);
    const uint32_t aQ = abase + OFF_Q;
    const uint32_t aK[2] = { abase + OFF_K0, abase + OFF_K1 };
    const uint32_t aV[2] = { abase + OFF_V0, abase + OFF_V1 };
    const uint32_t aP = abase + OFF_P;

    const int tid = threadIdx.x, wid = tid >> 5, lane = tid & 31;
    const int mi = wid >> 1, ni = wid & 1;
    const int b = blockIdx.y, i0 = blockIdx.x * 128;

    const int mat = lane >> 3, lr = lane & 7;
    const int arow = (mat & 1) * 8 + lr;
    const int asel = mat >> 1;
    const int brow = ((mat >> 1) << 3) + lr;
    const int bsel = mat & 1;

    const uint4* Qg4 = reinterpret_cast<const uint4*>(Qh_) + ((size_t)(b*SS + i0)) * 32;
    const uint4* Kg4 = reinterpret_cast<const uint4*>(Kh_) + (size_t)b*SS*32;
    const uint4* Vg4 = reinterpret_cast<const uint4*>(Vth_) + (size_t)b*DD*512;

    #pragma unroll
    for (int t = 0; t < 16; t++) {
        int idx = tid + t * 256;
        int r = idx >> 5, c = idx & 31;
        cpa16(tadr(aQ, r, c, 4), Qg4 + (size_t)r*32 + c);
    }
    CPA_COMMIT();
    #pragma unroll
    for (int t = 0; t < 8; t++) {
        int idx = tid + t * 256;
        int r = idx >> 5, c = idx & 31;
        cpa16(tadr(aK[0], r, c, 4), Kg4 + (size_t)r*32 + c);
    }
    CPA_COMMIT();
    #pragma unroll
    for (int t = 0; t < 8; t++) {
        int idx = tid + t * 256;
        int r = idx >> 3, c = idx & 7;
        cpa16(tadr(aV[0], r, c, 1), Vg4 + (size_t)r*512 + c);
    }
    CPA_COMMIT();

    float oacc[2][16][4];
    #pragma unroll
    for (int m2 = 0; m2 < 2; m2++)
        #pragma unroll
        for (int nf = 0; nf < 16; nf++)
            #pragma unroll
            for (int j = 0; j < 4; j++) oacc[m2][nf][j] = 0.0f;
    float lsum[2][2] = {{0.f,0.f},{0.f,0.f}};

    for (int kt = 0; kt < SS/64; kt++) {
        const int buf = kt & 1;
        __syncthreads();
        if (kt + 1 < SS/64) {
            const int nb = buf ^ 1;
            #pragma unroll
            for (int t = 0; t < 8; t++) {
                int idx = tid + t * 256;
                int r = idx >> 5, c = idx & 31;
                cpa16(tadr(aK[nb], r, c, 4), Kg4 + (size_t)((kt+1)*64 + r)*32 + c);
            }
            CPA_COMMIT();
            #pragma unroll
            for (int t = 0; t < 8; t++) {
                int idx = tid + t * 256;
                int r = idx >> 3, c = idx & 7;
                cpa16(tadr(aV[nb], r, c, 1), Vg4 + (size_t)r*512 + (kt+1)*8 + c);
            }
            CPA_COMMIT();
            CPA_WAIT(2);
        } else {
            CPA_WAIT(0);
        }
        __syncthreads();

        // ---- MMA1: S = Q K^T (warp tile 32x32) ----
        float sacc[2][4][4];
        #pragma unroll
        for (int m2 = 0; m2 < 2; m2++)
            #pragma unroll
            for (int nf = 0; nf < 4; nf++)
                #pragma unroll
                for (int j = 0; j < 4; j++) sacc[m2][nf][j] = 0.0f;

        #pragma unroll 4
        for (int ks = 0; ks < 16; ks++) {
            uint32_t a[2][4];
            #pragma unroll
            for (int m2 = 0; m2 < 2; m2++)
                LDMX4(a[m2][0],a[m2][1],a[m2][2],a[m2][3],
                      tadr(aQ, mi*32 + m2*16 + arow, 2*ks + asel, 4));
            #pragma unroll
            for (int n16 = 0; n16 < 2; n16++) {
                uint32_t b0,b1,b2,b3;
                LDMX4(b0,b1,b2,b3,
                      tadr(aK[buf], ni*32 + n16*16 + brow, 2*ks + bsel, 4));
                #pragma unroll
                for (int m2 = 0; m2 < 2; m2++) {
                    MMA16816(sacc[m2][n16*2  ], a[m2][0],a[m2][1],a[m2][2],a[m2][3], b0,b1);
                    MMA16816(sacc[m2][n16*2+1], a[m2][0],a[m2][1],a[m2][2],a[m2][3], b2,b3);
                }
            }
        }

        // ---- softmax: raw exp2 (log2e folded into Q scale) -> P fp16 ----
        {
            const int r0 = lane >> 2;
            const int ib = (lane & 3) * 4;
            #pragma unroll
            for (int m2 = 0; m2 < 2; m2++) {
                #pragma unroll
                for (int nf = 0; nf < 4; nf++) {
                    float e0 = ex2f(sacc[m2][nf][0]);
                    float e1 = ex2f(sacc[m2][nf][1]);
                    float e2 = ex2f(sacc[m2][nf][2]);
                    float e3 = ex2f(sacc[m2][nf][3]);
                    lsum[m2][0] += e0 + e1;
                    lsum[m2][1] += e2 + e3;
                    __half2 h01 = __floats2half2_rn(e0, e1);
                    __half2 h23 = __floats2half2_rn(e2, e3);
                    int row = mi*32 + m2*16 + r0;
                    sts32(tadr(aP, row,     ni*4 + nf, 1) + ib,
                          *reinterpret_cast<uint32_t*>(&h01));
                    sts32(tadr(aP, row + 8, ni*4 + nf, 1) + ib,
                          *reinterpret_cast<uint32_t*>(&h23));
                }
            }
        }
        // pair barrier: the 2 warps sharing rows mi*32..+32 exchange P halves
        asm volatile("bar.sync %0, %1;" :: "r"(mi + 1), "r"(64) : "memory");

        // ---- MMA2: O += P V (warp tile 32x128) ----
        #pragma unroll
        for (int ks = 0; ks < 4; ks++) {
            uint32_t a[2][4];
            #pragma unroll
            for (int m2 = 0; m2 < 2; m2++)
                LDMX4(a[m2][0],a[m2][1],a[m2][2],a[m2][3],
                      tadr(aP, mi*32 + m2*16 + arow, 2*ks + asel, 1));
            #pragma unroll
            for (int n16 = 0; n16 < 8; n16++) {
                uint32_t b0,b1,b2,b3;
                LDMX4(b0,b1,b2,b3,
                      tadr(aV[buf], ni*128 + n16*16 + brow, 2*ks + bsel, 1));
                #pragma unroll
                for (int m2 = 0; m2 < 2; m2++) {
                    MMA16816(oacc[m2][n16*2  ], a[m2][0],a[m2][1],a[m2][2],a[m2][3], b0,b1);
                    MMA16816(oacc[m2][n16*2+1], a[m2][0],a[m2][1],a[m2][2],a[m2][3], b2,b3);
                }
            }
        }
    }

    // ---- epilogue: combine lsum across ni pairs, mask, normalize, store ----
    __syncthreads();
    float* Lsh = reinterpret_cast<float*>(cbase + OFF_P);
    {
        const int r0 = lane >> 2;
        #pragma unroll
        for (int m2 = 0; m2 < 2; m2++)
            #pragma unroll
            for (int h = 0; h < 2; h++) {
                float v = lsum[m2][h];
                v += __shfl_xor_sync(0xffffffff, v, 1);
                v += __shfl_xor_sync(0xffffffff, v, 2);
                if ((lane & 3) == 0)
                    Lsh[(mi*32 + m2*16 + h*8 + r0)*2 + ni] = v;
            }
    }
    __syncthreads();
    {
        const int r0 = lane >> 2;
        #pragma unroll
        for (int m2 = 0; m2 < 2; m2++) {
            int row0 = mi*32 + m2*16 + r0;
            size_t g0 = (size_t)b*SS + i0 + row0;
            size_t g1 = g0 + 8;
            float l0 = Lsh[row0*2] + Lsh[row0*2 + 1];
            float l1 = Lsh[(row0+8)*2] + Lsh[(row0+8)*2 + 1];
            float mf0 = (q0g[g0] != 0.0f && k0g[g0] != 0.0f) ? (1.0f / l0) : 0.0f;
            float mf1 = (q0g[g1] != 0.0f && k0g[g1] != 0.0f) ? (1.0f / l1) : 0.0f;
            uint32_t* H0 = reinterpret_cast<uint32_t*>(O16 + g0*DD);
            uint32_t* H1 = reinterpret_cast<uint32_t*>(O16 + g1*DD);
            int cb = lane & 3;
            #pragma unroll
            for (int nf = 0; nf < 16; nf++) {
                int f2 = ni*64 + nf*4 + cb;
                __half2 a2 = __floats2half2_rn(oacc[m2][nf][0]*mf0, oacc[m2][nf][1]*mf0);
                __half2 c2 = __floats2half2_rn(oacc[m2][nf][2]*mf1, oacc[m2][nf][3]*mf1);
                H0[f2] = *reinterpret_cast<uint32_t*>(&a2);
                H1[f2] = *reinterpret_cast<uint32_t*>(&c2);
            }
        }
    }
}

// ---------------------------------------------------------------------------
extern "C" void kernel_launch(void* const* d_in, const int* in_sizes, int n_in,
                              void* d_out, int out_size)
{
    const float* src = (const float*)d_in[0];
    const float* Wq  = (const float*)d_in[1];
    const float* bq  = (const float*)d_in[2];
    const float* Wk  = (const float*)d_in[3];
    const float* bk  = (const float*)d_in[4];
    const float* Wv  = (const float*)d_in[5];
    const float* bv  = (const float*)d_in[6];
    const float* Wo  = (const float*)d_in[7];
    const float* bo  = (const float*)d_in[8];
    float* out = (float*)d_out;

    __half *pS,*pWq,*pWk,*pWv,*pWo,*pQ,*pK,*pV,*pO;
    float *pq0,*pk0;
    cudaGetSymbolAddress((void**)&pS, g_src16);
    cudaGetSymbolAddress((void**)&pWq, g_Wq16);
    cudaGetSymbolAddress((void**)&pWk, g_Wk16);
    cudaGetSymbolAddress((void**)&pWv, g_Wv16);
    cudaGetSymbolAddress((void**)&pWo, g_Wo16);
    cudaGetSymbolAddress((void**)&pQ, g_Qh);
    cudaGetSymbolAddress((void**)&pK, g_Kh);
    cudaGetSymbolAddress((void**)&pV, g_Vth);
    cudaGetSymbolAddress((void**)&pO, g_O16);
    cudaGetSymbolAddress((void**)&pq0, g_q0);
    cudaGetSymbolAddress((void**)&pk0, g_k0);

    cvt_kernel<<<(NN*DD/4 + 255)/256, 256>>>((const float4*)src, (uint2*)pS, NN*DD/4);
    cvt_w4<<<dim3(DD*DD/4/256, 4), 256>>>(
        (const float4*)Wq, (const float4*)Wk, (const float4*)Wv, (const float4*)Wo,
        (uint2*)pWq, (uint2*)pWk, (uint2*)pWv, (uint2*)pWo);

    cudaFuncSetAttribute(proj_qkv, cudaFuncAttributeMaxDynamicSharedMemorySize, QKV_SMEM);
    // Q scale = (1/sqrt(256)) * log2(e) -> softmax becomes raw exp2
    proj_qkv<<<dim3(NN/128, 2), 256, QKV_SMEM>>>(
        pS, pWq, pWk, pWv, bq, bk, bv, pQ, pK, pV, pq0, pk0, 0.0901684761047f);

    cudaFuncSetAttribute(flash_mma, cudaFuncAttributeMaxDynamicSharedMemorySize, FL_SMEM);
    flash_mma<<<dim3(SS/128, BB), 256, FL_SMEM>>>(pQ, pK, pV, pq0, pk0, pO);

    cudaFuncSetAttribute(proj1, cudaFuncAttributeMaxDynamicSharedMemorySize, PJ_SMEM);
    proj1<<<dim3(NN/128, DD/128), 256, PJ_SMEM>>>(pO, pWo, bo, out);
}